// round 2
// baseline (speedup 1.0000x reference)
#include <cuda_runtime.h>

// Rotation_11364483465564 — diagonal phase rotation.
//
// a^T a = diag(0..D-1)  =>  M = expm(i*pi*angle*a^T a) is diagonal,
// M[n] = exp(i*theta*n), theta = fl32(pi_f32 * angle).  kron(M, I2) applies
// phase n to rows 2n and 2n+1 of the (2D, B) complex state.
//
// R1 change: one warp per n. Each thread computes sincosf ONCE and applies it
// to 4 float4 elements (rows 2n and 2n+1, column halves lane and lane+32).
// This cuts the ~170-instruction accurate-sincosf expansion from 8192 warp
// executions to 2048, which was the dominant issue/latency cost.
//
// Precision: argument fl32(fl32(pi*angle) * n) — bit-identical to the
// reference's expm input rounding. Accurate sincosf (NOT __sincosf; fast
// MUFU reduction is too lossy at |arg| ~ 2e4).

#ifndef ROT_D
#define ROT_D 2048
#endif
#ifndef ROT_B
#define ROT_B 256
#endif

static constexpr int PLANE_FLOATS = 2 * ROT_D * ROT_B;   // 1,048,576
static constexpr int PLANE_VEC4   = PLANE_FLOATS / 4;    // 262,144
static constexpr int VEC4_PER_ROW = ROT_B / 4;           // 64

__global__ __launch_bounds__(256)
void rotation_phase_kernel(const float* __restrict__ angle,
                           const float* __restrict__ xr,
                           const float* __restrict__ xi,
                           float* __restrict__ out)
{
    const int tid  = blockIdx.x * blockDim.x + threadIdx.x;
    const int n    = tid >> 5;          // warp id == Fock index n (0..D-1)
    const int lane = tid & 31;

    // theta = fl32(pi_f32 * angle) — identical rounding to reference.
    const float theta = 3.14159265358979323846f * __ldg(angle);

    float s, c;
    sincosf(theta * (float)n, &s, &c);  // fl32(theta*n): matches reference arg

    // vec4 indices: rows 2n, 2n+1; columns lane and lane+32.
    const int base0 = (2 * n)     * VEC4_PER_ROW;
    const int base1 = (2 * n + 1) * VEC4_PER_ROW;
    const int idx[4] = { base0 + lane, base0 + lane + 32,
                         base1 + lane, base1 + lane + 32 };

    const float4* __restrict__ xr4 = reinterpret_cast<const float4*>(xr);
    const float4* __restrict__ xi4 = reinterpret_cast<const float4*>(xi);
    float4* __restrict__ out4 = reinterpret_cast<float4*>(out);

    // Front-batch all 8 loads for MLP.
    float4 r[4], im[4];
#pragma unroll
    for (int p = 0; p < 4; p++) r[p]  = xr4[idx[p]];
#pragma unroll
    for (int p = 0; p < 4; p++) im[p] = xi4[idx[p]];

#pragma unroll
    for (int p = 0; p < 4; p++) {
        float4 o_re, o_im;
        o_re.x = fmaf(c, r[p].x, -s * im[p].x);
        o_re.y = fmaf(c, r[p].y, -s * im[p].y);
        o_re.z = fmaf(c, r[p].z, -s * im[p].z);
        o_re.w = fmaf(c, r[p].w, -s * im[p].w);
        o_im.x = fmaf(s, r[p].x,  c * im[p].x);
        o_im.y = fmaf(s, r[p].y,  c * im[p].y);
        o_im.z = fmaf(s, r[p].z,  c * im[p].z);
        o_im.w = fmaf(s, r[p].w,  c * im[p].w);
        out4[idx[p]]              = o_re;
        out4[idx[p] + PLANE_VEC4] = o_im;
    }
}

extern "C" void kernel_launch(void* const* d_in, const int* in_sizes, int n_in,
                              void* d_out, int out_size)
{
    (void)in_sizes; (void)n_in; (void)out_size;
    const float* angle = (const float*)d_in[0];
    // d_in[1] ('a' matrix) unused: a^T a = diag(0..D-1) analytically.
    const float* xr = (const float*)d_in[2];
    const float* xi = (const float*)d_in[3];
    float* out = (float*)d_out;

    // 2048 warps (one per n) = 65536 threads = 256 blocks x 256 threads.
    const int threads = 256;
    const int blocks  = (ROT_D * 32) / threads;   // 256
    rotation_phase_kernel<<<blocks, threads>>>(angle, xr, xi, out);
}